// round 4
// baseline (speedup 1.0000x reference)
#include <cuda_runtime.h>
#include <cstdint>

#define NB    16384
#define DTC   0.1f
#define CH    8

// ---------------- smem layout (words) ----------------
// staging: 16 rows x 4 step-pairs x 128 filters x float2
#define STAGE_WORDS (16 * 1024)
#define MEAS_OFF    STAGE_WORDS            // [buf][m*2+half][f][4]
#define MEAS_BUF    2048
#define CTRL_OFF    (MEAS_OFF + 3 * MEAS_BUF)
#define CTRL_BUF    2048                   // [buf][q][f][4]
#define SMEM_WORDS  (CTRL_OFF + 3 * CTRL_BUF)
#define SMEM_BYTES  (SMEM_WORDS * 4)       // 114688 B

struct St  { float x0,x1,x2,x3,p00,p01,p02,p03,p11,p12,p13,p22,p23,p33; };
struct Cst { float q00,q01,q02,q03,q11,q12,q13,q22,q23,q33,r00,r01,r11; };

__device__ __forceinline__ void cp16(uint32_t dst, const float* src) {
    asm volatile("cp.async.ca.shared.global [%0], [%1], 16;\n" :: "r"(dst), "l"(src));
}

// sector-packed cooperative prefetch of one 8-step chunk (full)
__device__ __forceinline__ void issue_full(
    uint32_t su, const float* __restrict__ meas, const float* __restrict__ ctrl,
    int b0, int tid, int buf, int s0)
{
#pragma unroll
    for (int k = 0; k < 4; k++) {
        int id = tid + 128 * k;
        int half = id & 1, f = (id >> 1) & 127, m = id >> 8;
        cp16(su + (uint32_t)(MEAS_OFF + buf * MEAS_BUF + ((m * 2 + half) * 128 + f) * 4) * 4,
             meas + (size_t)(b0 + f) * 200 + m * 100 + s0 + 4 * half);
    }
#pragma unroll
    for (int k = 0; k < 4; k++) {
        int id = tid + 128 * k;
        int q = id & 3, f = id >> 2;
        cp16(su + (uint32_t)(CTRL_OFF + buf * CTRL_BUF + (q * 128 + f) * 4) * 4,
             ctrl + (size_t)(b0 + f) * 200 + 2 * s0 + 4 * q);
    }
    asm volatile("cp.async.commit_group;\n" ::: "memory");
}

// tail (4 steps at s0=96): only first halves / first two ctrl quarters
__device__ __forceinline__ void issue_tail(
    uint32_t su, const float* __restrict__ meas, const float* __restrict__ ctrl,
    int b0, int tid, int buf)
{
#pragma unroll
    for (int k = 0; k < 4; k++) {
        int id = tid + 128 * k;
        int half = id & 1, f = (id >> 1) & 127, m = id >> 8;
        if (half == 0)
            cp16(su + (uint32_t)(MEAS_OFF + buf * MEAS_BUF + ((m * 2) * 128 + f) * 4) * 4,
                 meas + (size_t)(b0 + f) * 200 + m * 100 + 96);
    }
#pragma unroll
    for (int k = 0; k < 4; k++) {
        int id = tid + 128 * k;
        int q = id & 3, f = id >> 2;
        if (q < 2)
            cp16(su + (uint32_t)(CTRL_OFF + buf * CTRL_BUF + (q * 128 + f) * 4) * 4,
                 ctrl + (size_t)(b0 + f) * 200 + 192 + 4 * q);
    }
    asm volatile("cp.async.commit_group;\n" ::: "memory");
}

__device__ __forceinline__ void ukf_step(
    St& s, const Cst& c, float z0, float z1, float ux, float uy, float* o)
{
    const float xp0 = s.x0 + DTC * s.x2 + 0.5f * DTC * DTC * ux;
    const float xp1 = s.x1 + DTC * s.x3 + 0.5f * DTC * DTC * uy;
    const float xp2 = s.x2 + DTC * ux;
    const float xp3 = s.x3 + DTC * uy;

    // A = M P M^T (exact collapse of the weighted sigma outer products)
    const float a02 = s.p02 + DTC * s.p22;
    const float a03 = s.p03 + DTC * s.p23;
    const float a12 = s.p12 + DTC * s.p23;
    const float a13 = s.p13 + DTC * s.p33;
    const float a00 = s.p00 + DTC * s.p02 + DTC * a02;
    const float a11 = s.p11 + DTC * s.p13 + DTC * a13;
    const float a01 = s.p01 + DTC * s.p03 + DTC * a12;

    const float s00 = a00 + c.r00;
    const float s01 = a01 + c.r01;
    const float s11 = a11 + c.r11;
    const float idet = __fdividef(1.0f, s00 * s11 - s01 * s01);
    const float i00 =  s11 * idet;
    const float i01 = -s01 * idet;
    const float i11 =  s00 * idet;

    const float K00 = a00 * i00 + a01 * i01, K01 = a00 * i01 + a01 * i11;
    const float K10 = a01 * i00 + a11 * i01, K11 = a01 * i01 + a11 * i11;
    const float K20 = a02 * i00 + a12 * i01, K21 = a02 * i01 + a12 * i11;
    const float K30 = a03 * i00 + a13 * i01, K31 = a03 * i01 + a13 * i11;

    const float in0 = z0 - xp0, in1 = z1 - xp1;
    const float xn0 = xp0 + K00 * in0 + K01 * in1;
    const float xn1 = xp1 + K10 * in0 + K11 * in1;
    const float xn2 = xp2 + K20 * in0 + K21 * in1;
    const float xn3 = xp3 + K30 * in0 + K31 * in1;

    const float KS00 = K00 * s00 + K01 * s01, KS01 = K00 * s01 + K01 * s11;
    const float KS10 = K10 * s00 + K11 * s01, KS11 = K10 * s01 + K11 * s11;
    const float KS20 = K20 * s00 + K21 * s01, KS21 = K20 * s01 + K21 * s11;
    const float KS30 = K30 * s00 + K31 * s01, KS31 = K30 * s01 + K31 * s11;

    s.p00 = a00 + c.q00 - (KS00 * K00 + KS01 * K01);
    s.p01 = a01 + c.q01 - (KS00 * K10 + KS01 * K11);
    s.p02 = a02 + c.q02 - (KS00 * K20 + KS01 * K21);
    s.p03 = a03 + c.q03 - (KS00 * K30 + KS01 * K31);
    s.p11 = a11 + c.q11 - (KS10 * K10 + KS11 * K11);
    s.p12 = a12 + c.q12 - (KS10 * K20 + KS11 * K21);
    s.p13 = a13 + c.q13 - (KS10 * K30 + KS11 * K31);
    s.p22 = s.p22 + c.q22 - (KS20 * K20 + KS21 * K21);
    s.p23 = s.p23 + c.q23 - (KS20 * K30 + KS21 * K31);
    s.p33 = s.p33 + c.q33 - (KS30 * K30 + KS31 * K31);
    s.x0 = xn0; s.x1 = xn1; s.x2 = xn2; s.x3 = xn3;

    o[0] = xp0;  o[1] = xp1;
    o[2] = xn0;  o[3] = xn1;  o[4] = xn2;  o[5] = xn3;
    o[6]  = s.p00; o[7]  = s.p01; o[8]  = s.p02; o[9]  = s.p03;
    o[10] = s.p11; o[11] = s.p12; o[12] = s.p13;
    o[13] = s.p22; o[14] = s.p23; o[15] = s.p33;
}

// compute NS steps (NS = 8 or 4) from input buffer `buf`, staging into smem
template <int NS>
__device__ __forceinline__ void compute_chunk(
    St& st, const Cst& c, float* sm, int buf, int tid)
{
    const float* mb = sm + MEAS_OFF + buf * MEAS_BUF;
    const float* cb = sm + CTRL_OFF + buf * CTRL_BUF;

    float4 z0a = *reinterpret_cast<const float4*>(mb + (0 * 128 + tid) * 4);
    float4 z1a = *reinterpret_cast<const float4*>(mb + (2 * 128 + tid) * 4);
    float4 c0  = *reinterpret_cast<const float4*>(cb + (0 * 128 + tid) * 4);
    float4 c1  = *reinterpret_cast<const float4*>(cb + (1 * 128 + tid) * 4);
    float4 z0b = z0a, z1b = z1a, c2 = c0, c3 = c1;
    if (NS == 8) {
        z0b = *reinterpret_cast<const float4*>(mb + (1 * 128 + tid) * 4);
        z1b = *reinterpret_cast<const float4*>(mb + (3 * 128 + tid) * 4);
        c2  = *reinterpret_cast<const float4*>(cb + (2 * 128 + tid) * 4);
        c3  = *reinterpret_cast<const float4*>(cb + (3 * 128 + tid) * 4);
    }
    const float z0s[8] = {z0a.x,z0a.y,z0a.z,z0a.w, z0b.x,z0b.y,z0b.z,z0b.w};
    const float z1s[8] = {z1a.x,z1a.y,z1a.z,z1a.w, z1b.x,z1b.y,z1b.z,z1b.w};
    const float uxs[8] = {c0.x,c0.z,c1.x,c1.z, c2.x,c2.z,c3.x,c3.z};
    const float uys[8] = {c0.y,c0.w,c1.y,c1.w, c2.y,c2.w,c3.y,c3.w};

    float prev[16];
#pragma unroll
    for (int sp = 0; sp < NS; sp++) {
        float cur[16];
        ukf_step(st, c, z0s[sp], z1s[sp], uxs[sp], uys[sp], cur);
        if (sp & 1) {
            float* sb = sm + (sp >> 1) * 256 + tid * 2;
#pragma unroll
            for (int r = 0; r < 16; r++)
                *reinterpret_cast<float2*>(sb + r * 1024) = make_float2(prev[r], cur[r]);
        } else {
#pragma unroll
            for (int r = 0; r < 16; r++) prev[r] = cur[r];
        }
    }
}

// output-row -> staged-row map (covs mirrored from upper triangle)
__device__ __forceinline__ int row_map(int R) {
    constexpr int MAP[22] = {0,1,2,3,4,5,
                             6,7,8,9, 7,10,11,12, 8,11,13,14, 9,12,14,15};
    return MAP[R];
}

__device__ __forceinline__ void flush_full(
    const float* __restrict__ sm, float* __restrict__ preds,
    float* __restrict__ states, float* __restrict__ covs,
    int blk, int tid, int s0)
{
#pragma unroll
    for (int p = 0; p < 2; p++) {
        const int t = tid + 128 * p;
        const int h = t & 1, f = t >> 1;
        const int gb = blk * 128 + f;
        const float* base = sm + f * 2 + h * 512;
        float* pp = preds  + (size_t)gb * 200  + s0 + 4 * h;
        float* ps = states + (size_t)gb * 400  + s0 + 4 * h;
        float* pc = covs   + (size_t)gb * 1600 + s0 + 4 * h;
#pragma unroll
        for (int R = 0; R < 22; R++) {
            const int r = row_map(R);
            float2 lo = *reinterpret_cast<const float2*>(base + r * 1024);
            float2 hi = *reinterpret_cast<const float2*>(base + r * 1024 + 256);
            float4 v = make_float4(lo.x, lo.y, hi.x, hi.y);
            float* dst = (R < 2) ? (pp + R * 100)
                       : (R < 6) ? (ps + (R - 2) * 100)
                                 : (pc + (R - 6) * 100);
            *reinterpret_cast<float4*>(dst) = v;
        }
    }
}

__global__ __launch_bounds__(128, 1) void ukf_kernel(
    const float* __restrict__ meas, const float* __restrict__ state0,
    const float* __restrict__ cov0, const float* __restrict__ ctrl,
    const float* __restrict__ Qm,   const float* __restrict__ Rm,
    float* __restrict__ preds, float* __restrict__ states, float* __restrict__ covs)
{
    extern __shared__ float sm[];
    const uint32_t su = (uint32_t)__cvta_generic_to_shared(sm);
    const int tid = threadIdx.x;
    const int b0  = blockIdx.x * 128;
    const int b   = b0 + tid;

    St st;
    {
        float4 xv = *reinterpret_cast<const float4*>(state0 + (size_t)b * 4);
        st.x0 = xv.x; st.x1 = xv.y; st.x2 = xv.z; st.x3 = xv.w;
        const float4* pv = reinterpret_cast<const float4*>(cov0 + (size_t)b * 16);
        float4 r0 = pv[0], r1 = pv[1], r2 = pv[2], r3 = pv[3];
        st.p00 = r0.x; st.p01 = r0.y; st.p02 = r0.z; st.p03 = r0.w;
        st.p11 = r1.y; st.p12 = r1.z; st.p13 = r1.w;
        st.p22 = r2.z; st.p23 = r2.w; st.p33 = r3.w;
    }
    Cst c;
    c.q00 = Qm[0];  c.q01 = Qm[1];  c.q02 = Qm[2];  c.q03 = Qm[3];
    c.q11 = Qm[5];  c.q12 = Qm[6];  c.q13 = Qm[7];
    c.q22 = Qm[10]; c.q23 = Qm[11]; c.q33 = Qm[15];
    c.r00 = Rm[0];  c.r01 = Rm[1];  c.r11 = Rm[3];

    issue_full(su, meas, ctrl, b0, tid, 0, 0);
    issue_full(su, meas, ctrl, b0, tid, 1, 8);

#pragma unroll 1
    for (int ch = 0; ch < 10; ch++) {
        asm volatile("cp.async.wait_group 1;\n" ::: "memory");
        __syncthreads();   // inputs(ch) visible to all; flush(ch-1) done -> staging reusable
        issue_full(su, meas, ctrl, b0, tid, (ch + 2) % 3, (ch + 2) * 8);
        compute_chunk<8>(st, c, sm, ch % 3, tid);
        __syncthreads();   // staging complete
        flush_full(sm, preds, states, covs, blockIdx.x, tid, ch * 8);
    }

    // chunk 10
    asm volatile("cp.async.wait_group 1;\n" ::: "memory");
    __syncthreads();
    issue_tail(su, meas, ctrl, b0, tid, 0);
    compute_chunk<8>(st, c, sm, 1, tid);
    __syncthreads();
    flush_full(sm, preds, states, covs, blockIdx.x, tid, 80);

    // chunk 11
    asm volatile("cp.async.wait_group 1;\n" ::: "memory");
    __syncthreads();
    compute_chunk<8>(st, c, sm, 2, tid);
    __syncthreads();
    flush_full(sm, preds, states, covs, blockIdx.x, tid, 88);

    // tail: 4 steps at s0 = 96
    asm volatile("cp.async.wait_group 0;\n" ::: "memory");
    __syncthreads();
    compute_chunk<4>(st, c, sm, 0, tid);
    __syncthreads();
    {
        const int f  = tid;
        const int gb = blockIdx.x * 128 + f;
        const float* base = sm + f * 2;
        float* pp = preds  + (size_t)gb * 200  + 96;
        float* ps = states + (size_t)gb * 400  + 96;
        float* pc = covs   + (size_t)gb * 1600 + 96;
#pragma unroll
        for (int R = 0; R < 22; R++) {
            const int r = row_map(R);
            float2 lo = *reinterpret_cast<const float2*>(base + r * 1024);
            float2 hi = *reinterpret_cast<const float2*>(base + r * 1024 + 256);
            float4 v = make_float4(lo.x, lo.y, hi.x, hi.y);
            float* dst = (R < 2) ? (pp + R * 100)
                       : (R < 6) ? (ps + (R - 2) * 100)
                                 : (pc + (R - 6) * 100);
            *reinterpret_cast<float4*>(dst) = v;
        }
    }
}

extern "C" void kernel_launch(void* const* d_in, const int* in_sizes, int n_in,
                              void* d_out, int out_size)
{
    const float* meas  = (const float*)d_in[0];
    const float* state = (const float*)d_in[1];
    const float* cov   = (const float*)d_in[2];
    const float* ctrl  = (const float*)d_in[3];
    const float* Q     = (const float*)d_in[4];
    const float* R     = (const float*)d_in[5];

    float* out    = (float*)d_out;
    float* preds  = out;                         // 16384*2*100
    float* states = preds  + (size_t)NB * 200;   // 16384*4*100
    float* covs   = states + (size_t)NB * 400;   // 16384*16*100

    static int smem_set = 0;
    if (!smem_set) {
        cudaFuncSetAttribute(ukf_kernel,
                             cudaFuncAttributeMaxDynamicSharedMemorySize, SMEM_BYTES);
        smem_set = 1;
    }

    ukf_kernel<<<NB / 128, 128, SMEM_BYTES>>>(meas, state, cov, ctrl, Q, R,
                                              preds, states, covs);
}

// round 5
// speedup vs baseline: 1.1226x; 1.1226x over previous
#include <cuda_runtime.h>
#include <cstdint>

#define NB     16384
#define DTC    0.1f
#define THREADS 64
#define FPT    2
#define FPB    128            // filters per block
#define CH     16

// ---------------- smem layout (words) ----------------
// staging: 16 rows x 8 pairs x 128 filters x float2 : r*2048 + p*256 + f*2
#define STAGE_WORDS 32768
#define MEAS_OFF    STAGE_WORDS          // [buf][(m*4+q)][f][4]
#define MEAS_BUF    4096
#define CTRL_OFF    (MEAS_OFF + 2 * MEAS_BUF)
#define CTRL_BUF    4096                 // [buf][q][f][4]
#define SMEM_WORDS  (CTRL_OFF + 2 * CTRL_BUF)
#define SMEM_BYTES  (SMEM_WORDS * 4)     // 196608 B

struct St  { float x0,x1,x2,x3,p00,p01,p02,p03,p11,p12,p13,p22,p23,p33; };
struct Cst { float q00,q01,q02,q03,q11,q12,q13,q22,q23,q33,r00,r01,r11; };

__device__ __forceinline__ void cp16(uint32_t dst, const float* src) {
    asm volatile("cp.async.ca.shared.global [%0], [%1], 16;\n" :: "r"(dst), "l"(src));
}

// full 16-step chunk input prefetch (sector-packed, cooperative)
__device__ __forceinline__ void issue_full(
    uint32_t su, const float* __restrict__ meas, const float* __restrict__ ctrl,
    int b0, int tid, int buf, int s0)
{
#pragma unroll
    for (int j = 0; j < 16; j++) {            // meas: 2m x 4q x 128f
        int id = tid + 64 * j;
        int f = id & 127, q = (id >> 7) & 3, m = id >> 9;
        cp16(su + (uint32_t)(MEAS_OFF + buf * MEAS_BUF + ((m * 4 + q) * 128 + f) * 4) * 4,
             meas + (size_t)(b0 + f) * 200 + m * 100 + s0 + 4 * q);
    }
#pragma unroll
    for (int j = 0; j < 16; j++) {            // ctrl: 8q x 128f
        int id = tid + 64 * j;
        int f = id & 127, q = id >> 7;
        cp16(su + (uint32_t)(CTRL_OFF + buf * CTRL_BUF + (q * 128 + f) * 4) * 4,
             ctrl + (size_t)(b0 + f) * 200 + 2 * s0 + 4 * q);
    }
    asm volatile("cp.async.commit_group;\n" ::: "memory");
}

// tail (4 steps at s0=96)
__device__ __forceinline__ void issue_tail(
    uint32_t su, const float* __restrict__ meas, const float* __restrict__ ctrl,
    int b0, int tid, int buf)
{
#pragma unroll
    for (int j = 0; j < 4; j++) {
        int id = tid + 64 * j;
        int f = id & 127, m = (id >> 7) & 1;
        cp16(su + (uint32_t)(MEAS_OFF + buf * MEAS_BUF + ((m * 4) * 128 + f) * 4) * 4,
             meas + (size_t)(b0 + f) * 200 + m * 100 + 96);
    }
#pragma unroll
    for (int j = 0; j < 4; j++) {
        int id = tid + 64 * j;
        int f = id & 127, q = (id >> 7) & 1;
        cp16(su + (uint32_t)(CTRL_OFF + buf * CTRL_BUF + (q * 128 + f) * 4) * 4,
             ctrl + (size_t)(b0 + f) * 200 + 192 + 4 * q);
    }
    asm volatile("cp.async.commit_group;\n" ::: "memory");
}

__device__ __forceinline__ void ukf_step(
    St& s, const Cst& c, float z0, float z1, float ux, float uy, float* o)
{
    const float xp0 = s.x0 + DTC * s.x2 + 0.5f * DTC * DTC * ux;
    const float xp1 = s.x1 + DTC * s.x3 + 0.5f * DTC * DTC * uy;
    const float xp2 = s.x2 + DTC * ux;
    const float xp3 = s.x3 + DTC * uy;

    // A = M P M^T (exact collapse of the weighted sigma outer products)
    const float a02 = s.p02 + DTC * s.p22;
    const float a03 = s.p03 + DTC * s.p23;
    const float a12 = s.p12 + DTC * s.p23;
    const float a13 = s.p13 + DTC * s.p33;
    const float a00 = s.p00 + DTC * s.p02 + DTC * a02;
    const float a11 = s.p11 + DTC * s.p13 + DTC * a13;
    const float a01 = s.p01 + DTC * s.p03 + DTC * a12;

    const float s00 = a00 + c.r00;
    const float s01 = a01 + c.r01;
    const float s11 = a11 + c.r11;
    const float idet = __fdividef(1.0f, s00 * s11 - s01 * s01);
    const float i00 =  s11 * idet;
    const float i01 = -s01 * idet;
    const float i11 =  s00 * idet;

    const float K00 = a00 * i00 + a01 * i01, K01 = a00 * i01 + a01 * i11;
    const float K10 = a01 * i00 + a11 * i01, K11 = a01 * i01 + a11 * i11;
    const float K20 = a02 * i00 + a12 * i01, K21 = a02 * i01 + a12 * i11;
    const float K30 = a03 * i00 + a13 * i01, K31 = a03 * i01 + a13 * i11;

    const float in0 = z0 - xp0, in1 = z1 - xp1;
    const float xn0 = xp0 + K00 * in0 + K01 * in1;
    const float xn1 = xp1 + K10 * in0 + K11 * in1;
    const float xn2 = xp2 + K20 * in0 + K21 * in1;
    const float xn3 = xp3 + K30 * in0 + K31 * in1;

    const float KS00 = K00 * s00 + K01 * s01, KS01 = K00 * s01 + K01 * s11;
    const float KS10 = K10 * s00 + K11 * s01, KS11 = K10 * s01 + K11 * s11;
    const float KS20 = K20 * s00 + K21 * s01, KS21 = K20 * s01 + K21 * s11;
    const float KS30 = K30 * s00 + K31 * s01, KS31 = K30 * s01 + K31 * s11;

    s.p00 = a00 + c.q00 - (KS00 * K00 + KS01 * K01);
    s.p01 = a01 + c.q01 - (KS00 * K10 + KS01 * K11);
    s.p02 = a02 + c.q02 - (KS00 * K20 + KS01 * K21);
    s.p03 = a03 + c.q03 - (KS00 * K30 + KS01 * K31);
    s.p11 = a11 + c.q11 - (KS10 * K10 + KS11 * K11);
    s.p12 = a12 + c.q12 - (KS10 * K20 + KS11 * K21);
    s.p13 = a13 + c.q13 - (KS10 * K30 + KS11 * K31);
    s.p22 = s.p22 + c.q22 - (KS20 * K20 + KS21 * K21);
    s.p23 = s.p23 + c.q23 - (KS20 * K30 + KS21 * K31);
    s.p33 = s.p33 + c.q33 - (KS30 * K30 + KS31 * K31);
    s.x0 = xn0; s.x1 = xn1; s.x2 = xn2; s.x3 = xn3;

    o[0] = xp0;  o[1] = xp1;
    o[2] = xn0;  o[3] = xn1;  o[4] = xn2;  o[5] = xn3;
    o[6]  = s.p00; o[7]  = s.p01; o[8]  = s.p02; o[9]  = s.p03;
    o[10] = s.p11; o[11] = s.p12; o[12] = s.p13;
    o[13] = s.p22; o[14] = s.p23; o[15] = s.p33;
}

// compute NG 4-step groups (NG = 4 full chunk, 1 tail), two chains per thread
template <int NG>
__device__ __forceinline__ void compute_chunk(
    St* s, const Cst& c, float* sm, int buf, int tid)
{
    const float* mb = sm + MEAS_OFF + buf * MEAS_BUF;
    const float* cb = sm + CTRL_OFF + buf * CTRL_BUF;

#pragma unroll
    for (int g = 0; g < NG; g++) {
        float4 z0[FPT], z1[FPT], cq0[FPT], cq1[FPT];
#pragma unroll
        for (int k = 0; k < FPT; k++) {
            const int fl = tid + 64 * k;
            z0[k]  = *reinterpret_cast<const float4*>(mb + ((0 + g) * 128 + fl) * 4);
            z1[k]  = *reinterpret_cast<const float4*>(mb + ((4 + g) * 128 + fl) * 4);
            cq0[k] = *reinterpret_cast<const float4*>(cb + ((2 * g) * 128 + fl) * 4);
            cq1[k] = *reinterpret_cast<const float4*>(cb + ((2 * g + 1) * 128 + fl) * 4);
        }

        float prev[FPT][16], cur[FPT][16];

        // steps 4g+0, 4g+1 -> pair 2g
#pragma unroll
        for (int k = 0; k < FPT; k++)
            ukf_step(s[k], c, z0[k].x, z1[k].x, cq0[k].x, cq0[k].y, prev[k]);
#pragma unroll
        for (int k = 0; k < FPT; k++)
            ukf_step(s[k], c, z0[k].y, z1[k].y, cq0[k].z, cq0[k].w, cur[k]);
#pragma unroll
        for (int k = 0; k < FPT; k++) {
            float* sb = sm + (2 * g) * 256 + (tid + 64 * k) * 2;
#pragma unroll
            for (int r = 0; r < 16; r++)
                *reinterpret_cast<float2*>(sb + r * 2048) =
                    make_float2(prev[k][r], cur[k][r]);
        }

        // steps 4g+2, 4g+3 -> pair 2g+1
#pragma unroll
        for (int k = 0; k < FPT; k++)
            ukf_step(s[k], c, z0[k].z, z1[k].z, cq1[k].x, cq1[k].y, prev[k]);
#pragma unroll
        for (int k = 0; k < FPT; k++)
            ukf_step(s[k], c, z0[k].w, z1[k].w, cq1[k].z, cq1[k].w, cur[k]);
#pragma unroll
        for (int k = 0; k < FPT; k++) {
            float* sb = sm + (2 * g + 1) * 256 + (tid + 64 * k) * 2;
#pragma unroll
            for (int r = 0; r < 16; r++)
                *reinterpret_cast<float2*>(sb + r * 2048) =
                    make_float2(prev[k][r], cur[k][r]);
        }
    }
}

__device__ __forceinline__ int row_map(int R) {
    constexpr int MAP[22] = {0,1,2,3,4,5,
                             6,7,8,9, 7,10,11,12, 8,11,13,14, 9,12,14,15};
    return MAP[R];
}

// flush one 16-step chunk: 64B contiguous per (row, filter)
__device__ __forceinline__ void flush_full(
    const float* __restrict__ sm, float* __restrict__ preds,
    float* __restrict__ states, float* __restrict__ covs,
    int blk, int tid, int s0)
{
#pragma unroll
    for (int it = 0; it < 8; it++) {
        const int idx = it * 64 + tid;
        const int f = idx >> 2, h = idx & 3;
        const int gb = blk * FPB + f;
        const float* base = sm + f * 2 + h * 512;      // pair 2h
        float* pp = preds  + (size_t)gb * 200  + s0 + 4 * h;
        float* ps = states + (size_t)gb * 400  + s0 + 4 * h;
        float* pc = covs   + (size_t)gb * 1600 + s0 + 4 * h;
#pragma unroll
        for (int R = 0; R < 22; R++) {
            const int r = row_map(R);
            float2 lo = *reinterpret_cast<const float2*>(base + r * 2048);
            float2 hi = *reinterpret_cast<const float2*>(base + r * 2048 + 256);
            float4 v = make_float4(lo.x, lo.y, hi.x, hi.y);
            float* dst = (R < 2) ? (pp + R * 100)
                       : (R < 6) ? (ps + (R - 2) * 100)
                                 : (pc + (R - 6) * 100);
            *reinterpret_cast<float4*>(dst) = v;
        }
    }
}

__global__ __launch_bounds__(THREADS, 1) void ukf_kernel(
    const float* __restrict__ meas, const float* __restrict__ state0,
    const float* __restrict__ cov0, const float* __restrict__ ctrl,
    const float* __restrict__ Qm,   const float* __restrict__ Rm,
    float* __restrict__ preds, float* __restrict__ states, float* __restrict__ covs)
{
    extern __shared__ float sm[];
    const uint32_t su = (uint32_t)__cvta_generic_to_shared(sm);
    const int tid = threadIdx.x;
    const int blk = blockIdx.x;
    const int b0  = blk * FPB;

    St s[FPT];
#pragma unroll
    for (int k = 0; k < FPT; k++) {
        const int b = b0 + tid + 64 * k;
        float4 xv = *reinterpret_cast<const float4*>(state0 + (size_t)b * 4);
        s[k].x0 = xv.x; s[k].x1 = xv.y; s[k].x2 = xv.z; s[k].x3 = xv.w;
        const float4* pv = reinterpret_cast<const float4*>(cov0 + (size_t)b * 16);
        float4 r0 = pv[0], r1 = pv[1], r2 = pv[2], r3 = pv[3];
        s[k].p00 = r0.x; s[k].p01 = r0.y; s[k].p02 = r0.z; s[k].p03 = r0.w;
        s[k].p11 = r1.y; s[k].p12 = r1.z; s[k].p13 = r1.w;
        s[k].p22 = r2.z; s[k].p23 = r2.w; s[k].p33 = r3.w;
    }
    Cst c;
    c.q00 = Qm[0];  c.q01 = Qm[1];  c.q02 = Qm[2];  c.q03 = Qm[3];
    c.q11 = Qm[5];  c.q12 = Qm[6];  c.q13 = Qm[7];
    c.q22 = Qm[10]; c.q23 = Qm[11]; c.q33 = Qm[15];
    c.r00 = Rm[0];  c.r01 = Rm[1];  c.r11 = Rm[3];

    issue_full(su, meas, ctrl, b0, tid, 0, 0);

#pragma unroll 1
    for (int ch = 0; ch < 6; ch++) {
        if (ch < 5) issue_full(su, meas, ctrl, b0, tid, (ch + 1) & 1, (ch + 1) * CH);
        else        issue_tail(su, meas, ctrl, b0, tid, 0);
        asm volatile("cp.async.wait_group 1;\n" ::: "memory");
        __syncthreads();                         // inputs(ch) ready; staging reusable
        compute_chunk<4>(s, c, sm, ch & 1, tid);
        __syncthreads();                         // staging complete
        flush_full(sm, preds, states, covs, blk, tid, ch * CH);
    }

    // tail: 4 steps at s0 = 96 (in buf 0)
    asm volatile("cp.async.wait_group 0;\n" ::: "memory");
    __syncthreads();
    compute_chunk<1>(s, c, sm, 0, tid);
    __syncthreads();
#pragma unroll
    for (int it = 0; it < 2; it++) {
        const int f  = it * 64 + tid;
        const int gb = blk * FPB + f;
        const float* base = sm + f * 2;
        float* pp = preds  + (size_t)gb * 200  + 96;
        float* ps = states + (size_t)gb * 400  + 96;
        float* pc = covs   + (size_t)gb * 1600 + 96;
#pragma unroll
        for (int R = 0; R < 22; R++) {
            const int r = row_map(R);
            float2 lo = *reinterpret_cast<const float2*>(base + r * 2048);
            float2 hi = *reinterpret_cast<const float2*>(base + r * 2048 + 256);
            float4 v = make_float4(lo.x, lo.y, hi.x, hi.y);
            float* dst = (R < 2) ? (pp + R * 100)
                       : (R < 6) ? (ps + (R - 2) * 100)
                                 : (pc + (R - 6) * 100);
            *reinterpret_cast<float4*>(dst) = v;
        }
    }
}

extern "C" void kernel_launch(void* const* d_in, const int* in_sizes, int n_in,
                              void* d_out, int out_size)
{
    const float* meas  = (const float*)d_in[0];
    const float* state = (const float*)d_in[1];
    const float* cov   = (const float*)d_in[2];
    const float* ctrl  = (const float*)d_in[3];
    const float* Q     = (const float*)d_in[4];
    const float* R     = (const float*)d_in[5];

    float* out    = (float*)d_out;
    float* preds  = out;                         // 16384*2*100
    float* states = preds  + (size_t)NB * 200;   // 16384*4*100
    float* covs   = states + (size_t)NB * 400;   // 16384*16*100

    static int smem_set = 0;
    if (!smem_set) {
        cudaFuncSetAttribute(ukf_kernel,
                             cudaFuncAttributeMaxDynamicSharedMemorySize, SMEM_BYTES);
        smem_set = 1;
    }

    ukf_kernel<<<NB / FPB, THREADS, SMEM_BYTES>>>(meas, state, cov, ctrl, Q, R,
                                                  preds, states, covs);
}